// round 6
// baseline (speedup 1.0000x reference)
#include <cuda_runtime.h>
#include <cstdint>

#define DINL __device__ __forceinline__

// ===================== problem dims =====================
#define M_TOT 4096
#define N_TOT 4096
#define K_TOT 4096
#define NUM_GROUPS 524288   // (4096*4096)/32

// ===================== GEMM tiling ======================
// CTA 128x256, 8 warps in 2(m) x 4(n), warp tile 64x64, BK=32.
#define BM 128
#define BN 256
#define BK 32
#define NKT (K_TOT / BK)                 // 128 k-tiles
#define STAGES 4
#define A_TILE_BYTES (BM * BK * 4)       // 16384
#define B_TILE_BYTES (BN * BK * 4)       // 32768
#define STAGE_BYTES (A_TILE_BYTES + B_TILE_BYTES)    // 49152
#define SMEM_HDR 1024
#define SMEM_TOTAL (SMEM_HDR + STAGES * STAGE_BYTES) // 197632

// 64MB + 64MB static scratch: fragment-major tiled tf32 operands
__device__ float g_A[16777216];
__device__ float g_W[16777216];

// ===================== helpers ==========================
DINL uint32_t smem_u32(const void* p) {
  uint32_t a;
  asm("{ .reg .u64 t; cvta.to.shared.u64 t, %1; cvt.u32.u64 %0, t; }" : "=r"(a) : "l"(p));
  return a;
}
DINL float tf32_rn(float f) {   // round-to-nearest tf32 (kills MMA truncation bias)
  uint32_t u;
  asm("cvt.rna.tf32.f32 %0, %1;" : "=r"(u) : "f"(f));
  return __uint_as_float(u);
}

#define MBAR_INIT(a, n) \
  asm volatile("mbarrier.init.shared.b64 [%0], %1;" :: "r"(a), "r"(n) : "memory")
#define MBAR_EXPECT_TX(a, b) \
  asm volatile("mbarrier.arrive.expect_tx.shared.b64 _, [%0], %1;" :: "r"(a), "r"(b) : "memory")
#define MBAR_ARRIVE(a) \
  asm volatile("mbarrier.arrive.shared.b64 _, [%0];" :: "r"(a) : "memory")

DINL void mbar_wait(uint32_t mbar, uint32_t parity) {
  asm volatile(
      "{\n\t.reg .pred P;\n\t"
      "W_%=:\n\t"
      "mbarrier.try_wait.parity.acquire.cta.shared::cta.b64 P, [%0], %1, 0x989680;\n\t"
      "@!P bra.uni W_%=;\n\t}"
      :: "r"(mbar), "r"(parity) : "memory");
}

DINL void bulk_g2s(uint32_t dst, const void* src, uint32_t bytes, uint32_t mbar) {
  asm volatile(
      "cp.async.bulk.shared::cta.global.mbarrier::complete_tx::bytes [%0], [%1], %2, [%3];"
      :: "r"(dst), "l"(src), "r"(bytes), "r"(mbar) : "memory");
}

#define LDS128(r, addr) \
  asm volatile("ld.shared.v4.b32 {%0,%1,%2,%3}, [%4];" \
               : "=r"((r)[0]), "=r"((r)[1]), "=r"((r)[2]), "=r"((r)[3]) : "r"(addr))

DINL void mma_tf32(float* d, const uint32_t* a, uint32_t b0, uint32_t b1) {
  asm volatile(
      "mma.sync.aligned.m16n8k8.row.col.f32.tf32.tf32.f32 "
      "{%0,%1,%2,%3}, {%4,%5,%6,%7}, {%8,%9}, {%0,%1,%2,%3};"
      : "+f"(d[0]), "+f"(d[1]), "+f"(d[2]), "+f"(d[3])
      : "r"(a[0]), "r"(a[1]), "r"(a[2]), "r"(a[3]), "r"(b0), "r"(b1));
}

// ===================== prep: x -> fragment-major tiled tf32 =====================
// g_A: [mtile(32)][kt(128)] tiles of 16KB.
// Tile = [kstep(4)][mfrag(8)][lane(32)][4 floats], matching the m16n8k8 A frag:
//   a0=(r,c) a1=(r+8,c) a2=(r,c+4) a3=(r+8,c+4), lane=(r&7)*4+(c&3).
__global__ void prep_x_kernel(const float* __restrict__ x) {
  const int idx = blockIdx.x * blockDim.x + threadIdx.x;  // float4 id
  const int m = idx >> 10;          // 1024 float4 per row of 4096
  const int c4 = idx & 1023;        // k0 = c4*4
  const int kt = c4 >> 3;
  const int kstep = (c4 >> 1) & 3;
  const int j4 = c4 & 1;            // c>=4 half
  float4 v = reinterpret_cast<const float4*>(x)[idx];
  float w[4] = {tf32_rn(v.x), tf32_rn(v.y), tf32_rn(v.z), tf32_rn(v.w)};
  const int mfrag = (m >> 4) & 7;
  const int idxhi = j4 * 2 + ((m >> 3) & 1);   // position inside 16B fragment
  float* tile = g_A + ((size_t)((m >> 7) * NKT + kt)) * (A_TILE_BYTES / 4);
  const int slot0 = (kstep * 8 + mfrag) * 32 + (m & 7) * 4;
#pragma unroll
  for (int j = 0; j < 4; j++) tile[(slot0 + j) * 4 + idxhi] = w[j];
}

// ===================== prep: dequant W -> fragment-major tiled tf32 =====================
// g_W: [ntile(16)][kt(128)] tiles of 32KB.
// Tile = [kstep(4)][pair(16)][lane(32)][4 floats] where each 16B packs two n8
// fragments: {fragEven b0,b1, fragOdd b0,b1}; B frag: b0=(k=lane&3, n=lane>>2),
// b1=(k=(lane&3)+4, n=lane>>2).
__global__ void dequant_kernel(const int4* __restrict__ q3, const float* __restrict__ norm) {
  const int g = blockIdx.x * blockDim.x + threadIdx.x;  // group id
  const int o = g >> 7;        // output feature (n)
  const int kg = g & 127;      // k-tile (GROUP_SIZE == BK)
  const float sc = norm[g];
  const float a = sc * (2.0f / 7.0f);
  const int4 pa = q3[g * 3 + 0];
  const int4 pb = q3[g * 3 + 1];
  const int4 pc = q3[g * 3 + 2];
  const unsigned b[12] = {(unsigned)pa.x, (unsigned)pa.y, (unsigned)pa.z, (unsigned)pa.w,
                          (unsigned)pb.x, (unsigned)pb.y, (unsigned)pb.z, (unsigned)pb.w,
                          (unsigned)pc.x, (unsigned)pc.y, (unsigned)pc.z, (unsigned)pc.w};
  const int nr = o & 255;
  const int pair = nr >> 4;
  const int half = (nr >> 3) & 1;
  const int ncol = nr & 7;
  float* tile = g_W + ((size_t)((o >> 8) * NKT + kg)) * (B_TILE_BYTES / 4);
#pragma unroll
  for (int t = 0; t < 4; t++) {   // t == kstep
    const unsigned b0 = b[3 * t + 0], b1 = b[3 * t + 1], b2 = b[3 * t + 2];
    unsigned v[8];
    v[0] = b0 & 7u;
    v[1] = (b0 >> 3) & 7u;
    v[2] = ((b0 >> 6) & 3u) | ((b1 & 1u) << 2);
    v[3] = (b1 >> 1) & 7u;
    v[4] = (b1 >> 4) & 7u;
    v[5] = ((b1 >> 7) & 1u) | ((b2 & 3u) << 1);
    v[6] = (b2 >> 2) & 7u;
    v[7] = (b2 >> 5) & 7u;
    const int base = (t * 16 + pair) * 32;
#pragma unroll
    for (int i = 0; i < 8; i++) {
      const float w = tf32_rn(fmaf((float)v[i], a, -sc));
      const int lane = ncol * 4 + (i & 3);
      tile[(base + lane) * 4 + half * 2 + (i >> 2)] = w;
    }
  }
}

// ===================== main GEMM =====================
__global__ void __launch_bounds__(256, 1)
gemm_kernel(const float* __restrict__ bias, float* __restrict__ out) {
  extern __shared__ __align__(1024) char smem[];
  const uint32_t sb = smem_u32(smem);
  const int tid = threadIdx.x;
  const int wid = tid >> 5;
  const int lane = tid & 31;
  const int wr = wid >> 2;   // 0..1 (m)
  const int wc = wid & 3;    // 0..3 (n)
  const int nt = blockIdx.x;  // 16
  const int mt = blockIdx.y;  // 32

  const uint32_t mb_full = sb;
  const uint32_t mb_empty = sb + 8 * STAGES;

  if (tid == 0) {
    for (int i = 0; i < STAGES; i++) {
      MBAR_INIT(mb_full + 8 * i, 1);
      MBAR_INIT(mb_empty + 8 * i, 256);
    }
    asm volatile("fence.proxy.async.shared::cta;" ::: "memory");
  }
  __syncthreads();

  const char* srcA = (const char*)g_A + (size_t)mt * NKT * A_TILE_BYTES;
  const char* srcB = (const char*)g_W + (size_t)nt * NKT * B_TILE_BYTES;

  if (tid == 0) {
#pragma unroll
    for (int s = 0; s < STAGES; s++) {
      const uint32_t full = mb_full + 8 * s;
      MBAR_EXPECT_TX(full, (uint32_t)STAGE_BYTES);
      const uint32_t dst = sb + SMEM_HDR + s * STAGE_BYTES;
      bulk_g2s(dst, srcA + (size_t)s * A_TILE_BYTES, A_TILE_BYTES, full);
      bulk_g2s(dst + A_TILE_BYTES, srcB + (size_t)s * B_TILE_BYTES, B_TILE_BYTES, full);
    }
  }

  float acc[4][8][4];
#pragma unroll
  for (int i = 0; i < 4; i++)
#pragma unroll
    for (int j = 0; j < 8; j++)
#pragma unroll
      for (int c = 0; c < 4; c++) acc[i][j][c] = 0.0f;

  const uint32_t a_lane_off = (wr * 4) * 32 * 16 + lane * 16;
  const uint32_t b_lane_off = (wc * 4) * 32 * 16 + lane * 16;

  for (int kt = 0; kt < NKT; kt++) {
    const int s = kt & (STAGES - 1);
    const uint32_t ph = (kt >> 2) & 1;
    mbar_wait(mb_full + 8 * s, ph);
    const uint32_t aB = sb + SMEM_HDR + s * STAGE_BYTES;
    const uint32_t bB = aB + A_TILE_BYTES;
#pragma unroll
    for (int ks = 0; ks < 4; ks++) {
      const uint32_t a_addr = aB + ks * (8 * 32 * 16) + a_lane_off;
      const uint32_t b_addr = bB + ks * (16 * 32 * 16) + b_lane_off;
      uint32_t af[4][4], bf[4][4];
#pragma unroll
      for (int mf = 0; mf < 4; mf++) LDS128(af[mf], a_addr + mf * 512);
#pragma unroll
      for (int p = 0; p < 4; p++) LDS128(bf[p], b_addr + p * 512);
#pragma unroll
      for (int mf = 0; mf < 4; mf++)
#pragma unroll
        for (int p = 0; p < 4; p++) {
          mma_tf32(acc[mf][2 * p + 0], af[mf], bf[p][0], bf[p][1]);
          mma_tf32(acc[mf][2 * p + 1], af[mf], bf[p][2], bf[p][3]);
        }
    }
    MBAR_ARRIVE(mb_empty + 8 * s);
    if (tid == 0) {
      const int kt2 = kt + STAGES;
      if (kt2 < NKT) {
        mbar_wait(mb_empty + 8 * s, ph);
        const uint32_t full = mb_full + 8 * s;
        MBAR_EXPECT_TX(full, (uint32_t)STAGE_BYTES);
        const uint32_t dst = sb + SMEM_HDR + s * STAGE_BYTES;
        bulk_g2s(dst, srcA + (size_t)kt2 * A_TILE_BYTES, A_TILE_BYTES, full);
        bulk_g2s(dst + A_TILE_BYTES, srcB + (size_t)kt2 * B_TILE_BYTES, B_TILE_BYTES, full);
      }
    }
  }

  // ---------------- epilogue: acc + bias -> out ----------------
  const int m_base = mt * BM + wr * 64 + (lane >> 2);
  const int n_base = nt * BN + wc * 64 + (lane & 3) * 2;
#pragma unroll
  for (int mf = 0; mf < 4; mf++) {
    const int m0 = m_base + mf * 16;
#pragma unroll
    for (int nf = 0; nf < 8; nf++) {
      const int n = n_base + nf * 8;
      const float2 bv = *reinterpret_cast<const float2*>(bias + n);
      float2 v0, v1;
      v0.x = acc[mf][nf][0] + bv.x;
      v0.y = acc[mf][nf][1] + bv.y;
      v1.x = acc[mf][nf][2] + bv.x;
      v1.y = acc[mf][nf][3] + bv.y;
      *reinterpret_cast<float2*>(out + (size_t)m0 * N_TOT + n) = v0;
      *reinterpret_cast<float2*>(out + (size_t)(m0 + 8) * N_TOT + n) = v1;
    }
  }
}

// ===================== launch =====================
extern "C" void kernel_launch(void* const* d_in, const int* in_sizes, int n_in,
                              void* d_out, int out_size) {
  const float* x    = (const float*)d_in[0];   // [2,2048,4096] f32
  const int4*  q3   = (const int4*)d_in[1];    // [NUM_GROUPS*12] int32 byte values
  const float* norm = (const float*)d_in[2];   // [NUM_GROUPS] f32
  const float* bias = (const float*)d_in[3];   // [4096] f32
  float* out = (float*)d_out;                  // [2,2048,4096] f32

  prep_x_kernel<<<(M_TOT * K_TOT / 4) / 256, 256>>>(x);
  dequant_kernel<<<NUM_GROUPS / 256, 256>>>(q3, norm);

  cudaFuncSetAttribute(gemm_kernel, cudaFuncAttributeMaxDynamicSharedMemorySize, SMEM_TOTAL);
  dim3 grid(N_TOT / BN, M_TOT / BM);
  gemm_kernel<<<grid, 256, SMEM_TOTAL>>>(bias, out);
}

// round 8
// speedup vs baseline: 1.9887x; 1.9887x over previous
#include <cuda_runtime.h>
#include <cuda_fp16.h>
#include <cstdint>

#define DINL __device__ __forceinline__

// ===================== problem dims =====================
#define M_TOT 4096
#define N_TOT 4096
#define K_TOT 4096
#define NUM_GROUPS 524288   // (4096*4096)/32

// ===================== GEMM tiling ======================
// CTA 128x256, 8 warps in 2(m) x 4(n), warp tile 64x64, BK=64 (fp16).
#define BM 128
#define BN 256
#define BK 64
#define NKT (K_TOT / BK)                 // 64 k-tiles
#define STAGES 4
#define A_TILE_BYTES (BM * BK * 2)       // 16384
#define B_TILE_BYTES (BN * BK * 2)       // 32768
#define STAGE_BYTES (A_TILE_BYTES + B_TILE_BYTES)    // 49152
#define SMEM_HDR 1024
#define SMEM_TOTAL (SMEM_HDR + STAGES * STAGE_BYTES) // 197632

// 32MB + 32MB static scratch: fragment-major tiled fp16 operands (as b32 pairs)
__device__ uint32_t g_A[8388608];
__device__ uint32_t g_W[8388608];
#define A_TILE_U32 4096   // 16KB tile
#define B_TILE_U32 8192   // 32KB tile

// ===================== helpers ==========================
DINL uint32_t smem_u32(const void* p) {
  uint32_t a;
  asm("{ .reg .u64 t; cvta.to.shared.u64 t, %1; cvt.u32.u64 %0, t; }" : "=r"(a) : "l"(p));
  return a;
}
DINL uint32_t pack_half2(float lo, float hi) {  // b32 = {hi:lo} fp16x2
  uint32_t u;
  asm("cvt.rn.f16x2.f32 %0, %1, %2;" : "=r"(u) : "f"(hi), "f"(lo));
  return u;
}

#define MBAR_INIT(a, n) \
  asm volatile("mbarrier.init.shared.b64 [%0], %1;" :: "r"(a), "r"(n) : "memory")
#define MBAR_EXPECT_TX(a, b) \
  asm volatile("mbarrier.arrive.expect_tx.shared.b64 _, [%0], %1;" :: "r"(a), "r"(b) : "memory")
#define MBAR_ARRIVE(a) \
  asm volatile("mbarrier.arrive.shared.b64 _, [%0];" :: "r"(a) : "memory")

DINL void mbar_wait(uint32_t mbar, uint32_t parity) {
  asm volatile(
      "{\n\t.reg .pred P;\n\t"
      "W_%=:\n\t"
      "mbarrier.try_wait.parity.acquire.cta.shared::cta.b64 P, [%0], %1, 0x989680;\n\t"
      "@!P bra.uni W_%=;\n\t}"
      :: "r"(mbar), "r"(parity) : "memory");
}

DINL void bulk_g2s(uint32_t dst, const void* src, uint32_t bytes, uint32_t mbar) {
  asm volatile(
      "cp.async.bulk.shared::cta.global.mbarrier::complete_tx::bytes [%0], [%1], %2, [%3];"
      :: "r"(dst), "l"(src), "r"(bytes), "r"(mbar) : "memory");
}

#define LDS128(r, addr) \
  asm volatile("ld.shared.v4.b32 {%0,%1,%2,%3}, [%4];" \
               : "=r"((r)[0]), "=r"((r)[1]), "=r"((r)[2]), "=r"((r)[3]) : "r"(addr))

DINL void mma_f16(float* d, const uint32_t* a, uint32_t b0, uint32_t b1) {
  asm volatile(
      "mma.sync.aligned.m16n8k16.row.col.f32.f16.f16.f32 "
      "{%0,%1,%2,%3}, {%4,%5,%6,%7}, {%8,%9}, {%0,%1,%2,%3};"
      : "+f"(d[0]), "+f"(d[1]), "+f"(d[2]), "+f"(d[3])
      : "r"(a[0]), "r"(a[1]), "r"(a[2]), "r"(a[3]), "r"(b0), "r"(b1));
}

// ===================== prep: x -> fragment-major tiled fp16 =====================
// g_A: [mtile(32)][kt(64)] tiles of 16KB.
// Tile = [ks(4)][mfrag(8)][lane(32)][4xb32], matching the m16n8k16 A frag:
//   a0=(r, 2c) a1=(r+8, 2c) a2=(r, 2c+8) a3=(r+8, 2c+8), lane=(r&7)*4+c.
__global__ void prep_x_kernel(const float* __restrict__ x) {
  const int idx = blockIdx.x * blockDim.x + threadIdx.x;  // float4 id
  const int m = idx >> 10;          // 1024 float4 per row of 4096
  const int c4 = idx & 1023;        // k0 = c4*4
  const int kt = c4 >> 4;
  const int ks = (c4 >> 2) & 3;
  const int kk = (c4 & 3) * 4;      // k within K=16 step: {0,4,8,12}
  float4 v = reinterpret_cast<const float4*>(x)[idx];
  const uint32_t h01 = pack_half2(v.x, v.y);
  const uint32_t h23 = pack_half2(v.z, v.w);
  const int r16 = m & 15;
  const int mfrag = (m >> 4) & 7;
  const int reg = (r16 >> 3) + ((kk >> 3) << 1);     // a0..a3 slot
  const int lane0 = (r16 & 7) * 4 + ((kk & 7) >> 1);
  uint32_t* tile = g_A + (size_t)((m >> 7) * NKT + kt) * A_TILE_U32;
  const int base = ((ks * 8 + mfrag) * 32) * 4;
  tile[base + lane0 * 4 + reg] = h01;
  tile[base + (lane0 + 1) * 4 + reg] = h23;
}

// ===================== prep: dequant W -> fragment-major tiled fp16 =====================
// g_W: [ntile(16)][kt(64)] tiles of 32KB.
// Tile = [ks(4)][pair(16)][lane(32)][4xb32]; each 16B packs two n8 B frags:
//   {fragEven.b0, fragEven.b1, fragOdd.b0, fragOdd.b1};
//   B frag: b0=(k=2(lane&3)+{0,1}, n=lane>>2), b1 same with k+8.
__global__ void dequant_kernel(const int4* __restrict__ q3, const float* __restrict__ norm) {
  const int g = blockIdx.x * blockDim.x + threadIdx.x;  // group id
  const int o = g >> 7;        // output feature (n)
  const int kg = g & 127;      // 32-wide k-group
  const float sc = norm[g];
  const float a = sc * (2.0f / 7.0f);
  const int4 pa = q3[g * 3 + 0];
  const int4 pb = q3[g * 3 + 1];
  const int4 pc = q3[g * 3 + 2];
  const unsigned b[12] = {(unsigned)pa.x, (unsigned)pa.y, (unsigned)pa.z, (unsigned)pa.w,
                          (unsigned)pb.x, (unsigned)pb.y, (unsigned)pb.z, (unsigned)pb.w,
                          (unsigned)pc.x, (unsigned)pc.y, (unsigned)pc.z, (unsigned)pc.w};
  const int nr = o & 255;
  const int pair = nr >> 4;
  const int nsub = (nr >> 3) & 1;    // which n8 frag in the 16B pack
  const int ncol = nr & 7;           // lane>>2
  uint32_t* tile = g_W + (size_t)((o >> 8) * NKT + (kg >> 1)) * B_TILE_U32;
#pragma unroll
  for (int t = 0; t < 4; t++) {   // triplet: 8 values, k = kg*32 + t*8 ..
    const unsigned b0 = b[3 * t + 0], b1 = b[3 * t + 1], b2 = b[3 * t + 2];
    unsigned v[8];
    v[0] = b0 & 7u;
    v[1] = (b0 >> 3) & 7u;
    v[2] = ((b0 >> 6) & 3u) | ((b1 & 1u) << 2);
    v[3] = (b1 >> 1) & 7u;
    v[4] = (b1 >> 4) & 7u;
    v[5] = ((b1 >> 7) & 1u) | ((b2 & 3u) << 1);
    v[6] = (b2 >> 2) & 7u;
    v[7] = (b2 >> 5) & 7u;
    const int ks = (kg & 1) * 2 + (t >> 1);
    const int reg = nsub * 2 + (t & 1);            // b0 vs b1 half, even/odd frag
    const int base = ((ks * 16 + pair) * 32) * 4;
#pragma unroll
    for (int i = 0; i < 8; i += 2) {
      const float w0 = fmaf((float)v[i], a, -sc);
      const float w1 = fmaf((float)v[i + 1], a, -sc);
      const int lane = ncol * 4 + (i >> 1);
      tile[base + lane * 4 + reg] = pack_half2(w0, w1);
    }
  }
}

// ===================== main GEMM =====================
__global__ void __launch_bounds__(256, 1)
gemm_kernel(const float* __restrict__ bias, float* __restrict__ out) {
  extern __shared__ __align__(1024) char smem[];
  const uint32_t sb = smem_u32(smem);
  const int tid = threadIdx.x;
  const int wid = tid >> 5;
  const int lane = tid & 31;
  const int wr = wid >> 2;   // 0..1 (m)
  const int wc = wid & 3;    // 0..3 (n)
  const int nt = blockIdx.x;  // 16
  const int mt = blockIdx.y;  // 32

  const uint32_t mb_full = sb;
  const uint32_t mb_empty = sb + 8 * STAGES;

  if (tid == 0) {
    for (int i = 0; i < STAGES; i++) {
      MBAR_INIT(mb_full + 8 * i, 1);
      MBAR_INIT(mb_empty + 8 * i, 256);
    }
    asm volatile("fence.proxy.async.shared::cta;" ::: "memory");
  }
  __syncthreads();

  const char* srcA = (const char*)(g_A + (size_t)mt * NKT * A_TILE_U32);
  const char* srcB = (const char*)(g_W + (size_t)nt * NKT * B_TILE_U32);

  if (tid == 0) {
#pragma unroll
    for (int s = 0; s < STAGES; s++) {
      const uint32_t full = mb_full + 8 * s;
      MBAR_EXPECT_TX(full, (uint32_t)STAGE_BYTES);
      const uint32_t dst = sb + SMEM_HDR + s * STAGE_BYTES;
      bulk_g2s(dst, srcA + (size_t)s * A_TILE_BYTES, A_TILE_BYTES, full);
      bulk_g2s(dst + A_TILE_BYTES, srcB + (size_t)s * B_TILE_BYTES, B_TILE_BYTES, full);
    }
  }

  float acc[4][8][4];
#pragma unroll
  for (int i = 0; i < 4; i++)
#pragma unroll
    for (int j = 0; j < 8; j++)
#pragma unroll
      for (int c = 0; c < 4; c++) acc[i][j][c] = 0.0f;

  const uint32_t a_lane_off = (wr * 4) * 512 + lane * 16;   // mfrag stride 512B
  const uint32_t b_lane_off = (wc * 4) * 512 + lane * 16;   // pair stride 512B

  for (int kt = 0; kt < NKT; kt++) {
    const int s = kt & (STAGES - 1);
    const uint32_t ph = (kt >> 2) & 1;
    mbar_wait(mb_full + 8 * s, ph);
    const uint32_t aB = sb + SMEM_HDR + s * STAGE_BYTES;
    const uint32_t bB = aB + A_TILE_BYTES;

    uint32_t af[2][4][4], bf[2][4][4];
    // prefetch ks=0
#pragma unroll
    for (int mf = 0; mf < 4; mf++) LDS128(af[0][mf], aB + a_lane_off + mf * 512);
#pragma unroll
    for (int p = 0; p < 4; p++) LDS128(bf[0][p], bB + b_lane_off + p * 512);

#pragma unroll
    for (int ks = 0; ks < 4; ks++) {
      const int cur = ks & 1, nxt = cur ^ 1;
      if (ks < 3) {
        const uint32_t a_addr = aB + (ks + 1) * (8 * 512) + a_lane_off;
        const uint32_t b_addr = bB + (ks + 1) * (16 * 512) + b_lane_off;
#pragma unroll
        for (int mf = 0; mf < 4; mf++) LDS128(af[nxt][mf], a_addr + mf * 512);
#pragma unroll
        for (int p = 0; p < 4; p++) LDS128(bf[nxt][p], b_addr + p * 512);
      }
#pragma unroll
      for (int mf = 0; mf < 4; mf++)
#pragma unroll
        for (int p = 0; p < 4; p++) {
          mma_f16(acc[mf][2 * p + 0], af[cur][mf], bf[cur][p][0], bf[cur][p][1]);
          mma_f16(acc[mf][2 * p + 1], af[cur][mf], bf[cur][p][2], bf[cur][p][3]);
        }
    }
    MBAR_ARRIVE(mb_empty + 8 * s);
    if (tid == 0) {
      const int kt2 = kt + STAGES;
      if (kt2 < NKT) {
        mbar_wait(mb_empty + 8 * s, ph);
        const uint32_t full = mb_full + 8 * s;
        MBAR_EXPECT_TX(full, (uint32_t)STAGE_BYTES);
        const uint32_t dst = sb + SMEM_HDR + s * STAGE_BYTES;
        bulk_g2s(dst, srcA + (size_t)kt2 * A_TILE_BYTES, A_TILE_BYTES, full);
        bulk_g2s(dst + A_TILE_BYTES, srcB + (size_t)kt2 * B_TILE_BYTES, B_TILE_BYTES, full);
      }
    }
  }

  // ---------------- epilogue: acc + bias -> out ----------------
  const int m_base = mt * BM + wr * 64 + (lane >> 2);
  const int n_base = nt * BN + wc * 64 + (lane & 3) * 2;
#pragma unroll
  for (int mf = 0; mf < 4; mf++) {
    const int m0 = m_base + mf * 16;
#pragma unroll
    for (int nf = 0; nf < 8; nf++) {
      const int n = n_base + nf * 8;
      const float2 bv = *reinterpret_cast<const float2*>(bias + n);
      float2 v0, v1;
      v0.x = acc[mf][nf][0] + bv.x;
      v0.y = acc[mf][nf][1] + bv.y;
      v1.x = acc[mf][nf][2] + bv.x;
      v1.y = acc[mf][nf][3] + bv.y;
      *reinterpret_cast<float2*>(out + (size_t)m0 * N_TOT + n) = v0;
      *reinterpret_cast<float2*>(out + (size_t)(m0 + 8) * N_TOT + n) = v1;
    }
  }
}

// ===================== launch =====================
extern "C" void kernel_launch(void* const* d_in, const int* in_sizes, int n_in,
                              void* d_out, int out_size) {
  const float* x    = (const float*)d_in[0];   // [2,2048,4096] f32
  const int4*  q3   = (const int4*)d_in[1];    // [NUM_GROUPS*12] int32 byte values
  const float* norm = (const float*)d_in[2];   // [NUM_GROUPS] f32
  const float* bias = (const float*)d_in[3];   // [4096] f32
  float* out = (float*)d_out;                  // [2,2048,4096] f32

  prep_x_kernel<<<(M_TOT * K_TOT / 4) / 256, 256>>>(x);
  dequant_kernel<<<NUM_GROUPS / 256, 256>>>(q3, norm);

  cudaFuncSetAttribute(gemm_kernel, cudaFuncAttributeMaxDynamicSharedMemorySize, SMEM_TOTAL);
  dim3 grid(N_TOT / BN, M_TOT / BM);
  gemm_kernel<<<grid, 256, SMEM_TOTAL>>>(bias, out);
}